// round 7
// baseline (speedup 1.0000x reference)
#include <cuda_runtime.h>
#include <math.h>

typedef unsigned long long u64;
#define DEV __device__ __forceinline__

constexpr int B = 4, TH = 120, STEPS = 8, D_IN = 32, D_MODEL = 512;
constexpr int N_HEADS = 8, N_LAYERS = 4, D_FF = 2048, N_SUB = 5;
constexpr int T = 128;          // TH + STEPS
constexpr int M = 512;          // B * T
constexpr float LN_EPS = 1e-5f;
constexpr float NEGMIN = -3.402823466e38f;
constexpr float EMB_SCALE = 22.627416997969522f;   // sqrt(512)
constexpr float INV_SQRT_DH = 0.125f;              // 1/sqrt(64)
constexpr int NB = 148;                            // persistent blocks (<= SM count)
constexpr int SMEM_BYTES = (128 * 68 + 32 * 132) * 4;  // 51712 (attn is max user)

// -------- device scratch (no allocations allowed) --------
__device__ float g_buf[B][T][D_IN];
__device__ float g_h[M][D_MODEL];
__device__ float g_q[M][D_MODEL];
__device__ float g_k[M][D_MODEL];
__device__ float g_v[M][D_MODEL];
__device__ float g_attn[M][D_MODEL];
__device__ float g_tmp[M][D_MODEL];
__device__ float g_ff[M][D_FF];
__device__ float g_cur[B][D_IN];
__device__ float g_ffr[B][D_FF];

// -------- software grid barrier (all NB blocks co-resident by construction) --
__device__ unsigned g_bar_count = 0;
__device__ volatile unsigned g_bar_gen = 0;

DEV void gbar() {
    __syncthreads();
    if (threadIdx.x == 0) {
        unsigned gen = g_bar_gen;
        __threadfence();                       // publish this block's writes
        if (atomicAdd(&g_bar_count, 1u) == gridDim.x - 1) {
            g_bar_count = 0;                   // reset BEFORE gen flip
            __threadfence();
            g_bar_gen = gen + 1;               // release
        } else {
            while (g_bar_gen == gen) { }       // spin on L2 line
        }
    }
    __syncthreads();
}

// -------- packed f32x2 helpers (bitwise == scalar FFMA) --------
DEV u64 pack2(float lo, float hi) {
    u64 r; asm("mov.b64 %0, {%1, %2};" : "=l"(r) : "f"(lo), "f"(hi)); return r;
}
DEV float2 unpack2(u64 v) {
    float2 r; asm("mov.b64 {%0, %1}, %2;" : "=f"(r.x), "=f"(r.y) : "l"(v)); return r;
}
DEV void fma2(u64& c, u64 a, u64 b) {
    asm("fma.rn.f32x2 %0, %1, %2, %0;" : "+l"(c) : "l"(a), "l"(b));
}
union F4U { float4 f; u64 u[2]; };

// L2 (bypass-L1) loads for cross-block intermediates
DEV float4 ldcg4(const float* p) { return __ldcg((const float4*)p); }
DEV float  ldcg1(const float* p) { return __ldcg(p); }

DEV float gelu_fast(float x) {
    // tanh(u) = 1 - 2/(e^{2u}+1); exact limits at +-inf, ~1e-7 rel err
    float w = 1.5957691216057308f * (x + 0.044715f * x * x * x);  // 2*0.7978845608*(...)
    float t = 1.0f - 2.0f / (__expf(w) + 1.0f);
    return 0.5f * x * (1.0f + t);
}

// =============== stage: embedding + positional encoding ===============
DEV void embed_stage(float* smbase, const float* __restrict__ Wemb,
                     const float* __restrict__ bemb) {
    float* xs = smbase;
    int tid = threadIdx.x;
    for (int row = blockIdx.x; row < M; row += gridDim.x) {
        int t = row & (T - 1);
        int b = row >> 7;
        __syncthreads();
        if (tid < 32) xs[tid] = ldcg1(&g_buf[b][t][tid]);
        __syncthreads();
#pragma unroll
        for (int c = 0; c < 2; c++) {
            int d = tid + c * 256;
            const float* w = Wemb + d * 32;
            float s = 0.0f;
#pragma unroll
            for (int i = 0; i < 32; i += 4) {
                float4 wv = __ldg((const float4*)&w[i]);
                s += wv.x * xs[i] + wv.y * xs[i + 1] + wv.z * xs[i + 2] + wv.w * xs[i + 3];
            }
            s = (s + __ldg(&bemb[d])) * EMB_SCALE;
            int j2 = d & ~1;
            float ang = (float)t * expf((float)j2 * (-9.210340371976184f / 512.0f));
            s += (d & 1) ? cosf(ang) : sinf(ang);
            g_h[row][d] = s;
        }
    }
}

// =============== stage: GEMM C[M,N] = A[M,K] @ W[N,K]^T (+ epilogue) ========
// EPI: 0 none | 1 gelu(c+bias) | 2 c+res | 3 c+bias+res ; BM fixed 64
template <int BN, int EPI, int NZ>
DEV void gemm_stage(float* smbase,
                    const float* __restrict__ A,
                    const float* __restrict__ W0, const float* __restrict__ W1,
                    const float* __restrict__ W2,
                    float* __restrict__ O0, float* __restrict__ O1,
                    float* __restrict__ O2,
                    const float* __restrict__ bias, const float* __restrict__ res,
                    int N, int K) {
    constexpr int BM = 64, TM = 4, TN = BN / 16;
    float (*As)[BM + 4] = (float(*)[BM + 4])smbase;
    float (*Ws)[BN + 4] = (float(*)[BN + 4])(smbase + 16 * (BM + 4));
    int tid = threadIdx.x;
    int tx = tid & 15, ty = tid >> 4;
    int lm = tid >> 2, kq = tid & 3;
    int tilesN = N / BN;
    int jobsZ = tilesN * (M / BM);
    bool wp = (BN == 64) || (tid < BN * 4);

    for (int job = blockIdx.x; job < jobsZ * NZ; job += gridDim.x) {
        int z = 0, tIdx = job;
        if (NZ > 1) { z = job / jobsZ; tIdx = job - z * jobsZ; }
        const float* __restrict__ W = (z == 0) ? W0 : (z == 1 ? W1 : W2);
        float* __restrict__ O = (z == 0) ? O0 : (z == 1 ? O1 : O2);
        int n0 = (tIdx % tilesN) * BN;
        int m0 = (tIdx / tilesN) * BM;

        u64 acc[TM][TN / 2];
#pragma unroll
        for (int i = 0; i < TM; i++)
#pragma unroll
            for (int j = 0; j < TN / 2; j++) acc[i][j] = pack2(0.0f, 0.0f);

        const float* Ap = &A[(m0 + lm) * K + kq * 4];
        const float* Wp = &W[(n0 + lm) * K + kq * 4];
        F4U av, wv;
        av.f = ldcg4(Ap);
        if (wp) wv.f = __ldg((const float4*)Wp);

        for (int kt = 0; kt < K; kt += 16) {
            As[kq * 4 + 0][lm] = av.f.x; As[kq * 4 + 1][lm] = av.f.y;
            As[kq * 4 + 2][lm] = av.f.z; As[kq * 4 + 3][lm] = av.f.w;
            if (wp) {
                Ws[kq * 4 + 0][lm] = wv.f.x; Ws[kq * 4 + 1][lm] = wv.f.y;
                Ws[kq * 4 + 2][lm] = wv.f.z; Ws[kq * 4 + 3][lm] = wv.f.w;
            }
            __syncthreads();
            if (kt + 16 < K) {
                av.f = ldcg4(Ap + kt + 16);
                if (wp) wv.f = __ldg((const float4*)(Wp + kt + 16));
            }
#pragma unroll
            for (int kk = 0; kk < 16; kk++) {
                u64 w2[TN / 2];
                if (TN == 2) {
                    w2[0] = *(const u64*)&Ws[kk][tx * 2];
                } else {
                    F4U wr; wr.f = *(const float4*)&Ws[kk][tx * 4];
                    w2[0] = wr.u[0]; w2[1] = wr.u[1];
                }
                F4U ar; ar.f = *(const float4*)&As[kk][ty * 4];
                float a4[4] = {ar.f.x, ar.f.y, ar.f.z, ar.f.w};
#pragma unroll
                for (int i = 0; i < TM; i++) {
                    u64 a2 = pack2(a4[i], a4[i]);
#pragma unroll
                    for (int j = 0; j < TN / 2; j++) fma2(acc[i][j], a2, w2[j]);
                }
            }
            __syncthreads();
        }

        int col = n0 + tx * TN;
#pragma unroll
        for (int i = 0; i < TM; i++) {
            int row = m0 + ty * TM + i;
            float c[TN];
#pragma unroll
            for (int j = 0; j < TN / 2; j++) {
                float2 p = unpack2(acc[i][j]);
                c[j * 2] = p.x; c[j * 2 + 1] = p.y;
            }
            if (EPI == 1) {
#pragma unroll
                for (int j = 0; j < TN; j++) c[j] = gelu_fast(c[j] + __ldg(&bias[col + j]));
            } else if (EPI == 2) {
#pragma unroll
                for (int j = 0; j < TN; j++) c[j] += ldcg1(&res[row * N + col + j]);
            } else if (EPI == 3) {
#pragma unroll
                for (int j = 0; j < TN; j++)
                    c[j] += ldcg1(&res[row * N + col + j]) + __ldg(&bias[col + j]);
            }
            if (TN == 4) {
                float4 o4 = {c[0], c[1], c[2], c[3]};
                *(float4*)&O[row * N + col] = o4;
            } else {
                float2 o2 = {c[0], c[1]};
                *(float2*)&O[row * N + col] = o2;
            }
        }
    }
}

// =============== stage: LayerNorm, warp-per-row (D=512) ===============
DEV void ln_stage(const float* __restrict__ X, const float* __restrict__ gam,
                  const float* __restrict__ bet, float* __restrict__ O) {
    int gw = (blockIdx.x << 3) + (threadIdx.x >> 5);
    int lane = threadIdx.x & 31;
    for (int row = gw; row < M; row += (gridDim.x << 3)) {
        float4 x[4];
        float s = 0.0f;
#pragma unroll
        for (int i = 0; i < 4; i++) {
            x[i] = ldcg4(&X[row * 512 + lane * 4 + i * 128]);
            s += x[i].x + x[i].y + x[i].z + x[i].w;
        }
#pragma unroll
        for (int o = 16; o; o >>= 1) s += __shfl_xor_sync(~0u, s, o);
        float mu = s * (1.0f / 512.0f);
        float v = 0.0f;
#pragma unroll
        for (int i = 0; i < 4; i++) {
            x[i].x -= mu; x[i].y -= mu; x[i].z -= mu; x[i].w -= mu;
            v += x[i].x * x[i].x + x[i].y * x[i].y + x[i].z * x[i].z + x[i].w * x[i].w;
        }
#pragma unroll
        for (int o = 16; o; o >>= 1) v += __shfl_xor_sync(~0u, v, o);
        float inv = 1.0f / sqrtf(v * (1.0f / 512.0f) + LN_EPS);
#pragma unroll
        for (int i = 0; i < 4; i++) {
            int col = lane * 4 + i * 128;
            float4 g4 = __ldg((const float4*)&gam[col]);
            float4 b4 = __ldg((const float4*)&bet[col]);
            float4 o4;
            o4.x = x[i].x * inv * g4.x + b4.x;
            o4.y = x[i].y * inv * g4.y + b4.y;
            o4.z = x[i].z * inv * g4.z + b4.z;
            o4.w = x[i].w * inv * g4.w + b4.w;
            *(float4*)&O[row * 512 + col] = o4;
        }
    }
}

// =============== stage: attention, 128 jobs = (b,h,q-quarter of 32) =========
// threads: qr = tid>>3 (32 q-rows), kg = tid&7 (8 key-groups).
// QK keys interleaved k = kg + 8t -> per-instr the 8 kg lanes hit 8 distinct
// float4 bank-groups (68*8 == 0 mod 32, 4*kg spread). PV: thread kg owns dim
// float4s at col 4*kg + 32*c -> 8 distinct float4 = all 32 banks. No conflicts.
// mask: attend where key index > query index (anti-causal, faithful to source)
DEV void attn_stage(float* smbase) {
    float (*Ks)[68] = (float(*)[68])smbase;
    float (*Ps)[132] = (float(*)[132])(smbase + 128 * 68);
    int tid = threadIdx.x;
    int qr = tid >> 3, kg = tid & 7;
    for (int job = blockIdx.x; job < 128; job += gridDim.x) {
        int b = job >> 5, h = (job >> 2) & 7, qt = job & 3;
        int base = b * T, hc = h * 64;
        int qi = qt * 32 + qr;

        for (int i = tid; i < 2048; i += 256) {
            int r = i >> 4, c = i & 15;
            *(float4*)&Ks[r][c * 4] = ldcg4(&g_k[base + r][hc + c * 4]);
        }
        F4U q[16];
#pragma unroll
        for (int c = 0; c < 16; c++)
            q[c].f = ldcg4(&g_q[base + qi][hc + c * 4]);
        __syncthreads();

        float sreg[16];
        float mloc = NEGMIN;
#pragma unroll
        for (int t = 0; t < 16; t++) {
            int k = kg + 8 * t;
            u64 a0 = pack2(0.f, 0.f), a1 = a0, a2 = a0, a3 = a0;
#pragma unroll
            for (int c = 0; c < 16; c += 2) {
                F4U k0; k0.f = *(const float4*)&Ks[k][c * 4];
                F4U k1; k1.f = *(const float4*)&Ks[k][c * 4 + 4];
                fma2(a0, q[c].u[0], k0.u[0]);
                fma2(a1, q[c].u[1], k0.u[1]);
                fma2(a2, q[c + 1].u[0], k1.u[0]);
                fma2(a3, q[c + 1].u[1], k1.u[1]);
            }
            float2 p0 = unpack2(a0), p1 = unpack2(a1), p2 = unpack2(a2), p3 = unpack2(a3);
            float s = (p0.x + p0.y) + (p1.x + p1.y) + (p2.x + p2.y) + (p3.x + p3.y);
            s = (k > qi) ? s * INV_SQRT_DH : NEGMIN;
            sreg[t] = s;
            mloc = fmaxf(mloc, s);
        }
        mloc = fmaxf(mloc, __shfl_xor_sync(~0u, mloc, 1));
        mloc = fmaxf(mloc, __shfl_xor_sync(~0u, mloc, 2));
        mloc = fmaxf(mloc, __shfl_xor_sync(~0u, mloc, 4));
        float lsum = 0.0f;
#pragma unroll
        for (int t = 0; t < 16; t++) {
            float p = __expf(sreg[t] - mloc);
            Ps[qr][kg + 8 * t] = p;
            lsum += p;
        }
        lsum += __shfl_xor_sync(~0u, lsum, 1);
        lsum += __shfl_xor_sync(~0u, lsum, 2);
        lsum += __shfl_xor_sync(~0u, lsum, 4);
        float invl = 1.0f / lsum;

        __syncthreads();   // K reads + Ps writes complete
        for (int i = tid; i < 2048; i += 256) {
            int r = i >> 4, c = i & 15;
            *(float4*)&Ks[r][c * 4] = ldcg4(&g_v[base + r][hc + c * 4]);
        }
        __syncthreads();

        F4U o[2];
        o[0].u[0] = pack2(0.f, 0.f); o[0].u[1] = pack2(0.f, 0.f);
        o[1].u[0] = pack2(0.f, 0.f); o[1].u[1] = pack2(0.f, 0.f);
#pragma unroll 4
        for (int k = 0; k < 128; k++) {
            float p = Ps[qr][k];
            u64 p2 = pack2(p, p);
#pragma unroll
            for (int c = 0; c < 2; c++) {
                F4U v; v.f = *(const float4*)&Ks[k][kg * 4 + c * 32];
                fma2(o[c].u[0], p2, v.u[0]);
                fma2(o[c].u[1], p2, v.u[1]);
            }
        }
#pragma unroll
        for (int c = 0; c < 2; c++) {
            float4 r4;
            r4.x = o[c].f.x * invl; r4.y = o[c].f.y * invl;
            r4.z = o[c].f.z * invl; r4.w = o[c].f.w * invl;
            *(float4*)&g_attn[base + qi][hc + kg * 4 + c * 32] = r4;
        }
        __syncthreads();   // done with smem before next job
    }
}

// =============== stage: refine A (comb -> gelu(Wr1@comb)) ===============
DEV void refineA_stage(float* smbase, const float* __restrict__ Wemb,
                       const float* __restrict__ bemb,
                       const float* __restrict__ Wr1,
                       const float* __restrict__ br1, int step, int first) {
    if (blockIdx.x >= 64) return;
    float* comb = smbase;            // 1024 floats
    float* cur = smbase + 1024;      // 32 floats
    int b = blockIdx.x >> 4, part = blockIdx.x & 15;
    int tid = threadIdx.x;
    int ptr = TH + step;
    if (tid < 32)
        cur[tid] = first ? ldcg1(&g_buf[b][ptr - 1][tid]) : ldcg1(&g_cur[b][tid]);
    __syncthreads();
    for (int d = tid; d < 512; d += 256) {
        const float* w = &Wemb[d * 32];
        float s = 0.0f;
#pragma unroll
        for (int i = 0; i < 32; i += 4) {
            float4 wv = __ldg((const float4*)&w[i]);
            s += wv.x * cur[i] + wv.y * cur[i + 1] + wv.z * cur[i + 2] + wv.w * cur[i + 3];
        }
        comb[d] = (s + __ldg(&bemb[d])) * EMB_SCALE;
    }
    for (int d = tid; d < 512; d += 256)
        comb[512 + d] = ldcg1(&g_h[b * T + ptr - 1][d]);
    __syncthreads();

    int r = part * 128 + (tid >> 1);
    int half = tid & 1;
    const float* w = &Wr1[r * 1024 + half * 512];
    const float* cb = &comb[half * 512];
    u64 a0 = pack2(0.f, 0.f), a1 = pack2(0.f, 0.f);
    for (int i = 0; i < 512; i += 4) {
        F4U wv; wv.f = __ldg((const float4*)&w[i]);
        F4U cv; cv.f = *(const float4*)&cb[i];
        fma2(a0, wv.u[0], cv.u[0]);
        fma2(a1, wv.u[1], cv.u[1]);
    }
    float2 x0 = unpack2(a0), x1 = unpack2(a1);
    float s = x0.x + x0.y + x1.x + x1.y;
    s += __shfl_xor_sync(~0u, s, 1);
    if (half == 0) g_ffr[b][r] = gelu_fast(s + __ldg(&br1[r]));
    __syncthreads();
}

// =============== stage: refine B (delta + cur update) ===============
DEV void refineB_stage(float* smbase, const float* __restrict__ Wr2,
                       const float* __restrict__ br2, float* __restrict__ out,
                       int step, int first, int last) {
    if (blockIdx.x >= 4) return;
    float* ff = smbase;   // 2048 floats
    int b = blockIdx.x;
    int tid = threadIdx.x;
    for (int i = tid; i < 2048; i += 256) ff[i] = ldcg1(&g_ffr[b][i]);
    __syncthreads();
    int i = tid >> 3, part = tid & 7;
    const float* w = &Wr2[i * 2048 + part * 256];
    const float* f = &ff[part * 256];
    u64 a0 = pack2(0.f, 0.f), a1 = pack2(0.f, 0.f);
    for (int j = 0; j < 256; j += 4) {
        F4U wv; wv.f = __ldg((const float4*)&w[j]);
        F4U fv; fv.f = *(const float4*)&f[j];
        fma2(a0, wv.u[0], fv.u[0]);
        fma2(a1, wv.u[1], fv.u[1]);
    }
    float2 x0 = unpack2(a0), x1 = unpack2(a1);
    float s = x0.x + x0.y + x1.x + x1.y;
    s += __shfl_xor_sync(~0u, s, 1);
    s += __shfl_xor_sync(~0u, s, 2);
    s += __shfl_xor_sync(~0u, s, 4);
    if (part == 0) {
        int ptr = TH + step;
        float basev = first ? ldcg1(&g_buf[b][ptr - 1][i]) : ldcg1(&g_cur[b][i]);
        float nv = basev + s + __ldg(&br2[i]);
        g_cur[b][i] = nv;
        if (last) {
            g_buf[b][ptr][i] = nv;
            out[(b * STEPS + step) * D_IN + i] = nv;
        }
    }
    __syncthreads();
}

// =============== the single persistent kernel ===============
__global__ void __launch_bounds__(256, 1) mega_kernel(
    const float* __restrict__ history,
    const float* __restrict__ Wemb, const float* __restrict__ bemb,
    const float* __restrict__ Wq, const float* __restrict__ Wk,
    const float* __restrict__ Wv, const float* __restrict__ Wo,
    const float* __restrict__ ln1g, const float* __restrict__ ln1b,
    const float* __restrict__ W1, const float* __restrict__ b1,
    const float* __restrict__ W2, const float* __restrict__ b2,
    const float* __restrict__ ln2g, const float* __restrict__ ln2b,
    const float* __restrict__ Wr1, const float* __restrict__ br1,
    const float* __restrict__ Wr2, const float* __restrict__ br2,
    float* __restrict__ out) {
    extern __shared__ float sm[];
    int tid = threadIdx.x;

    // buf init
    if (blockIdx.x < B) {
        int b = blockIdx.x;
        for (int idx = tid; idx < T * D_IN; idx += 256) {
            int t = idx >> 5, i = idx & 31;
            g_buf[b][t][i] = (t < TH) ? history[(b * TH + t) * D_IN + i] : 0.0f;
        }
    }
    gbar();

    for (int step = 0; step < STEPS; step++) {
        embed_stage(sm, Wemb, bemb);
        gbar();
        for (int l = 0; l < N_LAYERS; l++) {
            const float* wq = Wq + l * D_MODEL * D_MODEL;
            const float* wk = Wk + l * D_MODEL * D_MODEL;
            const float* wv = Wv + l * D_MODEL * D_MODEL;
            const float* wo = Wo + l * D_MODEL * D_MODEL;
            const float* w1 = W1 + l * D_FF * D_MODEL;
            const float* w2 = W2 + l * D_MODEL * D_FF;

            gemm_stage<32, 0, 3>(sm, &g_h[0][0], wq, wk, wv,
                                 &g_q[0][0], &g_k[0][0], &g_v[0][0],
                                 nullptr, nullptr, 512, 512);
            gbar();
            attn_stage(sm);
            gbar();
            gemm_stage<32, 2, 1>(sm, &g_attn[0][0], wo, wo, wo,
                                 &g_tmp[0][0], &g_tmp[0][0], &g_tmp[0][0],
                                 nullptr, &g_h[0][0], 512, 512);
            gbar();
            ln_stage(&g_tmp[0][0], ln1g + l * 512, ln1b + l * 512, &g_h[0][0]);
            gbar();
            gemm_stage<64, 1, 1>(sm, &g_h[0][0], w1, w1, w1,
                                 &g_ff[0][0], &g_ff[0][0], &g_ff[0][0],
                                 b1 + l * D_FF, nullptr, 2048, 512);
            gbar();
            gemm_stage<32, 3, 1>(sm, &g_ff[0][0], w2, w2, w2,
                                 &g_tmp[0][0], &g_tmp[0][0], &g_tmp[0][0],
                                 b2 + l * 512, &g_h[0][0], 512, 2048);
            gbar();
            ln_stage(&g_tmp[0][0], ln2g + l * 512, ln2b + l * 512, &g_h[0][0]);
            gbar();
        }
        for (int s = 0; s < N_SUB; s++) {
            refineA_stage(sm, Wemb, bemb, Wr1, br1, step, s == 0);
            gbar();
            refineB_stage(sm, Wr2, br2, out, step, s == 0, s == N_SUB - 1);
            gbar();
        }
    }
}

// =============== host orchestration: ONE launch ===============
extern "C" void kernel_launch(void* const* d_in, const int* in_sizes, int n_in,
                              void* d_out, int out_size) {
    int o = (n_in >= 20) ? 1 : 0;   // "steps" scalar occupies index 1 if present
    const float* history = (const float*)d_in[0];
    const float* Wemb = (const float*)d_in[1 + o];
    const float* bemb = (const float*)d_in[2 + o];
    const float* Wq = (const float*)d_in[3 + o];
    const float* Wk = (const float*)d_in[4 + o];
    const float* Wv = (const float*)d_in[5 + o];
    const float* Wv_ = Wv;
    const float* Wo = (const float*)d_in[6 + o];
    const float* ln1g = (const float*)d_in[7 + o];
    const float* ln1b = (const float*)d_in[8 + o];
    const float* W1 = (const float*)d_in[9 + o];
    const float* b1 = (const float*)d_in[10 + o];
    const float* W2 = (const float*)d_in[11 + o];
    const float* b2 = (const float*)d_in[12 + o];
    const float* ln2g = (const float*)d_in[13 + o];
    const float* ln2b = (const float*)d_in[14 + o];
    const float* Wr1 = (const float*)d_in[15 + o];
    const float* br1 = (const float*)d_in[16 + o];
    const float* Wr2 = (const float*)d_in[17 + o];
    const float* br2 = (const float*)d_in[18 + o];
    float* out = (float*)d_out;
    (void)Wv_;

    cudaFuncSetAttribute(mega_kernel, cudaFuncAttributeMaxDynamicSharedMemorySize,
                         SMEM_BYTES);
    mega_kernel<<<NB, 256, SMEM_BYTES>>>(history, Wemb, bemb, Wq, Wk, Wv, Wo,
                                         ln1g, ln1b, W1, b1, W2, b2, ln2g, ln2b,
                                         Wr1, br1, Wr2, br2, out);
}

// round 8
// speedup vs baseline: 1.4997x; 1.4997x over previous
#include <cuda_runtime.h>
#include <math.h>

typedef unsigned long long u64;
#define DEV __device__ __forceinline__

constexpr int B = 4, TH = 120, STEPS = 8, D_IN = 32, D_MODEL = 512;
constexpr int N_HEADS = 8, N_LAYERS = 4, D_FF = 2048, N_SUB = 5;
constexpr int T = 128;          // TH + STEPS
constexpr int M = 512;          // B * T
constexpr float LN_EPS = 1e-5f;
constexpr float NEGMIN = -3.402823466e38f;
constexpr float EMB_SCALE = 22.627416997969522f;   // sqrt(512)
constexpr float INV_SQRT_DH = 0.125f;              // 1/sqrt(64)
constexpr int ATTN_SMEM = (128 * 68 + 32 * 132) * 4;  // 51712 bytes

// -------- device scratch (no allocations allowed) --------
__device__ float g_buf[B][T][D_IN];
__device__ float g_h[M][D_MODEL];
__device__ float g_q[M][D_MODEL];
__device__ float g_k[M][D_MODEL];
__device__ float g_v[M][D_MODEL];
__device__ float g_q2[M][D_MODEL];   // split-K half-1 partials
__device__ float g_k2[M][D_MODEL];
__device__ float g_v2[M][D_MODEL];
__device__ float g_attn[M][D_MODEL];
__device__ float g_part[4][M][D_MODEL];  // Wo / FFN2 split-K partials
__device__ float g_ff[M][D_FF];
__device__ float g_cur[B][D_IN];
__device__ float g_ffr[B][D_FF];

// -------- packed f32x2 helpers (bitwise == scalar FFMA) --------
DEV u64 pack2(float lo, float hi) {
    u64 r; asm("mov.b64 %0, {%1, %2};" : "=l"(r) : "f"(lo), "f"(hi)); return r;
}
DEV float2 unpack2(u64 v) {
    float2 r; asm("mov.b64 {%0, %1}, %2;" : "=f"(r.x), "=f"(r.y) : "l"(v)); return r;
}
DEV void fma2(u64& c, u64 a, u64 b) {
    asm("fma.rn.f32x2 %0, %1, %2, %0;" : "+l"(c) : "l"(a), "l"(b));
}
union F4U { float4 f; u64 u[2]; };

DEV float4 ldg4(const float* p) { return __ldg((const float4*)p); }

DEV float gelu_fast(float x) {
    float w = 1.5957691216057308f * (x + 0.044715f * x * x * x);
    float t = 1.0f - 2.0f / (__expf(w) + 1.0f);
    return 0.5f * x * (1.0f + t);
}

struct O6 { float* p[6]; };
struct P4 { const float* p[4]; };

// =============== buf init ===============
__global__ void init_buf_kernel(const float* __restrict__ history) {
    int b = blockIdx.x;
    for (int idx = threadIdx.x; idx < T * D_IN; idx += blockDim.x) {
        int t = idx >> 5, i = idx & 31;
        g_buf[b][t][i] = (t < TH) ? history[(b * TH + t) * D_IN + i] : 0.0f;
    }
}

// =============== embedding + positional encoding ===============
__global__ void embed_kernel(const float* __restrict__ Wemb,
                             const float* __restrict__ bemb) {
    int row = blockIdx.x;
    int t = row & (T - 1);
    int b = row >> 7;
    __shared__ float xs[D_IN];
    int tid = threadIdx.x;             // 128
    if (tid < D_IN) xs[tid] = g_buf[b][t][tid];
    __syncthreads();
#pragma unroll
    for (int c = 0; c < 4; c++) {
        int d = tid + c * 128;
        const float* w = Wemb + d * D_IN;
        float s = 0.0f;
#pragma unroll
        for (int i = 0; i < 32; i += 4) {
            float4 wv = ldg4(&w[i]);
            s += wv.x * xs[i] + wv.y * xs[i + 1] + wv.z * xs[i + 2] + wv.w * xs[i + 3];
        }
        s = (s + __ldg(&bemb[d])) * EMB_SCALE;
        int j2 = d & ~1;
        float ang = (float)t * expf((float)j2 * (-9.210340371976184f / 512.0f));
        s += (d & 1) ? cosf(ang) : sinf(ang);
        g_h[row][d] = s;
    }
}

// =============== GEMM v2: 64x64 tiles, TM4xTN4, double-buffered smem ========
// C_partial[M, 64-tile of N] = A[:, koff:koff+KS] @ W[:, koff:koff+KS]^T
// z -> (mat = z/NSPLIT selects W0/W1/W2, split = z%NSPLIT selects K-range and
// output partial buffer outs.p[z]).  EPI: 0 plain store | 1 gelu(c+bias)
template <int NSPLIT, int EPI>
__global__ void __launch_bounds__(256, 2) gemm2_kernel(
    const float* __restrict__ A, const float* __restrict__ W0,
    const float* __restrict__ W1, const float* __restrict__ W2,
    O6 outs, const float* __restrict__ bias, int N, int Kfull, int KS) {
    __shared__ __align__(16) float As[2][16][68];
    __shared__ __align__(16) float Ws[2][16][68];
    int z = blockIdx.z;
    int mat = z / NSPLIT, split = z - mat * NSPLIT;
    const float* __restrict__ W = (mat == 0) ? W0 : (mat == 1 ? W1 : W2);
    float* __restrict__ O = outs.p[z];
    int koff = split * KS;
    int tid = threadIdx.x;
    int tx = tid & 15, ty = tid >> 4;
    int m0 = blockIdx.y * 64, n0 = blockIdx.x * 64;
    int lm = tid >> 2, kq = tid & 3;

    u64 acc[4][2];
#pragma unroll
    for (int i = 0; i < 4; i++) { acc[i][0] = pack2(0.f, 0.f); acc[i][1] = acc[i][0]; }

    const float* Ap = A + (m0 + lm) * Kfull + koff + kq * 4;
    const float* Wp = W + (n0 + lm) * Kfull + koff + kq * 4;
    F4U av, wv;
    av.f = ldg4(Ap);
    wv.f = ldg4(Wp);
    // stage tile 0 into buffer 0
    As[0][kq * 4 + 0][lm] = av.f.x; As[0][kq * 4 + 1][lm] = av.f.y;
    As[0][kq * 4 + 2][lm] = av.f.z; As[0][kq * 4 + 3][lm] = av.f.w;
    Ws[0][kq * 4 + 0][lm] = wv.f.x; Ws[0][kq * 4 + 1][lm] = wv.f.y;
    Ws[0][kq * 4 + 2][lm] = wv.f.z; Ws[0][kq * 4 + 3][lm] = wv.f.w;
    __syncthreads();

    int cur = 0;
    for (int kt = 0; kt < KS; kt += 16) {
        bool more = (kt + 16) < KS;
        if (more) {
            av.f = ldg4(Ap + kt + 16);
            wv.f = ldg4(Wp + kt + 16);
        }
#pragma unroll
        for (int kk = 0; kk < 16; kk++) {
            F4U wr; wr.f = *(const float4*)&Ws[cur][kk][tx * 4];
            F4U ar; ar.f = *(const float4*)&As[cur][kk][ty * 4];
            float a4[4] = {ar.f.x, ar.f.y, ar.f.z, ar.f.w};
#pragma unroll
            for (int i = 0; i < 4; i++) {
                u64 a2 = pack2(a4[i], a4[i]);
                fma2(acc[i][0], a2, wr.u[0]);
                fma2(acc[i][1], a2, wr.u[1]);
            }
        }
        if (more) {
            int nxt = cur ^ 1;
            As[nxt][kq * 4 + 0][lm] = av.f.x; As[nxt][kq * 4 + 1][lm] = av.f.y;
            As[nxt][kq * 4 + 2][lm] = av.f.z; As[nxt][kq * 4 + 3][lm] = av.f.w;
            Ws[nxt][kq * 4 + 0][lm] = wv.f.x; Ws[nxt][kq * 4 + 1][lm] = wv.f.y;
            Ws[nxt][kq * 4 + 2][lm] = wv.f.z; Ws[nxt][kq * 4 + 3][lm] = wv.f.w;
        }
        __syncthreads();
        cur ^= 1;
    }

    int col = n0 + tx * 4;
#pragma unroll
    for (int i = 0; i < 4; i++) {
        int row = m0 + ty * 4 + i;
        float2 c01 = unpack2(acc[i][0]);
        float2 c23 = unpack2(acc[i][1]);
        float c[4] = {c01.x, c01.y, c23.x, c23.y};
        if (EPI == 1) {
#pragma unroll
            for (int j = 0; j < 4; j++) c[j] = gelu_fast(c[j] + __ldg(&bias[col + j]));
        }
        float4 o4 = {c[0], c[1], c[2], c[3]};
        *(float4*)&O[row * N + col] = o4;
    }
}

// =============== fused LayerNorm: LN(res + sum(partials) (+ bias)) =========
// warp per row; block 128 thr = 4 rows; grid 128
template <int NP, bool HB>
__global__ void ln_fuse_kernel(const float* __restrict__ X, P4 P,
                               const float* __restrict__ bias,
                               const float* __restrict__ gam,
                               const float* __restrict__ bet,
                               float* __restrict__ O) {
    int row = blockIdx.x * 4 + (threadIdx.x >> 5);
    int lane = threadIdx.x & 31;
    float4 x[4];
    float s = 0.0f;
#pragma unroll
    for (int i = 0; i < 4; i++) {
        int col = lane * 4 + i * 128;
        x[i] = ldg4(&X[row * 512 + col]);
#pragma unroll
        for (int j = 0; j < NP; j++) {
            float4 pv = ldg4(&P.p[j][row * 512 + col]);
            x[i].x += pv.x; x[i].y += pv.y; x[i].z += pv.z; x[i].w += pv.w;
        }
        if (HB) {
            float4 b4 = ldg4(&bias[col]);
            x[i].x += b4.x; x[i].y += b4.y; x[i].z += b4.z; x[i].w += b4.w;
        }
        s += x[i].x + x[i].y + x[i].z + x[i].w;
    }
#pragma unroll
    for (int o = 16; o; o >>= 1) s += __shfl_xor_sync(~0u, s, o);
    float mu = s * (1.0f / 512.0f);
    float v = 0.0f;
#pragma unroll
    for (int i = 0; i < 4; i++) {
        x[i].x -= mu; x[i].y -= mu; x[i].z -= mu; x[i].w -= mu;
        v += x[i].x * x[i].x + x[i].y * x[i].y + x[i].z * x[i].z + x[i].w * x[i].w;
    }
#pragma unroll
    for (int o = 16; o; o >>= 1) v += __shfl_xor_sync(~0u, v, o);
    float inv = 1.0f / sqrtf(v * (1.0f / 512.0f) + LN_EPS);
#pragma unroll
    for (int i = 0; i < 4; i++) {
        int col = lane * 4 + i * 128;
        float4 g4 = ldg4(&gam[col]);
        float4 b4 = ldg4(&bet[col]);
        float4 o4;
        o4.x = x[i].x * inv * g4.x + b4.x;
        o4.y = x[i].y * inv * g4.y + b4.y;
        o4.z = x[i].z * inv * g4.z + b4.z;
        o4.w = x[i].w * inv * g4.w + b4.w;
        *(float4*)&O[row * 512 + col] = o4;
    }
}

// =============== Attention: 256 thr = qr32 x kg8, conflict-free layouts =====
// Sums the two split-K qkv partial halves during staging.
// mask: attend where key index > query index (anti-causal, faithful to source)
__global__ void __launch_bounds__(256) attn_kernel() {
    extern __shared__ float sm[];
    float (*Ks)[68] = (float(*)[68])sm;
    float (*Ps)[132] = (float(*)[132])(sm + 128 * 68);
    int tid = threadIdx.x;
    int qr = tid >> 3, kg = tid & 7;
    int bx = blockIdx.x;
    int b = bx >> 5, h = (bx >> 2) & 7, qt = bx & 3;
    int base = b * T, hc = h * 64;
    int qi = qt * 32 + qr;

    // stage K = k_half0 + k_half1
    for (int i = tid; i < 2048; i += 256) {
        int r = i >> 4, c = i & 15;
        float4 a = ldg4(&g_k[base + r][hc + c * 4]);
        float4 d = ldg4(&g_k2[base + r][hc + c * 4]);
        float4 sum = {a.x + d.x, a.y + d.y, a.z + d.z, a.w + d.w};
        *(float4*)&Ks[r][c * 4] = sum;
    }
    F4U q[16];
#pragma unroll
    for (int c = 0; c < 16; c++) {
        float4 a = ldg4(&g_q[base + qi][hc + c * 4]);
        float4 d = ldg4(&g_q2[base + qi][hc + c * 4]);
        q[c].f = make_float4(a.x + d.x, a.y + d.y, a.z + d.z, a.w + d.w);
    }
    __syncthreads();

    float sreg[16];
    float mloc = NEGMIN;
#pragma unroll
    for (int t = 0; t < 16; t++) {
        int k = kg + 8 * t;
        u64 a0 = pack2(0.f, 0.f), a1 = a0, a2 = a0, a3 = a0;
#pragma unroll
        for (int c = 0; c < 16; c += 2) {
            F4U k0; k0.f = *(const float4*)&Ks[k][c * 4];
            F4U k1; k1.f = *(const float4*)&Ks[k][c * 4 + 4];
            fma2(a0, q[c].u[0], k0.u[0]);
            fma2(a1, q[c].u[1], k0.u[1]);
            fma2(a2, q[c + 1].u[0], k1.u[0]);
            fma2(a3, q[c + 1].u[1], k1.u[1]);
        }
        float2 p0 = unpack2(a0), p1 = unpack2(a1), p2 = unpack2(a2), p3 = unpack2(a3);
        float s = (p0.x + p0.y) + (p1.x + p1.y) + (p2.x + p2.y) + (p3.x + p3.y);
        s = (k > qi) ? s * INV_SQRT_DH : NEGMIN;
        sreg[t] = s;
        mloc = fmaxf(mloc, s);
    }
    mloc = fmaxf(mloc, __shfl_xor_sync(~0u, mloc, 1));
    mloc = fmaxf(mloc, __shfl_xor_sync(~0u, mloc, 2));
    mloc = fmaxf(mloc, __shfl_xor_sync(~0u, mloc, 4));
    float lsum = 0.0f;
#pragma unroll
    for (int t = 0; t < 16; t++) {
        float p = __expf(sreg[t] - mloc);
        Ps[qr][kg + 8 * t] = p;
        lsum += p;
    }
    lsum += __shfl_xor_sync(~0u, lsum, 1);
    lsum += __shfl_xor_sync(~0u, lsum, 2);
    lsum += __shfl_xor_sync(~0u, lsum, 4);
    float invl = 1.0f / lsum;

    __syncthreads();
    // stage V = v_half0 + v_half1
    for (int i = tid; i < 2048; i += 256) {
        int r = i >> 4, c = i & 15;
        float4 a = ldg4(&g_v[base + r][hc + c * 4]);
        float4 d = ldg4(&g_v2[base + r][hc + c * 4]);
        float4 sum = {a.x + d.x, a.y + d.y, a.z + d.z, a.w + d.w};
        *(float4*)&Ks[r][c * 4] = sum;
    }
    __syncthreads();

    F4U o[2];
    o[0].u[0] = pack2(0.f, 0.f); o[0].u[1] = o[0].u[0];
    o[1].u[0] = o[0].u[0]; o[1].u[1] = o[0].u[0];
#pragma unroll 4
    for (int k = 0; k < 128; k++) {
        float p = Ps[qr][k];
        u64 p2 = pack2(p, p);
#pragma unroll
        for (int c = 0; c < 2; c++) {
            F4U v; v.f = *(const float4*)&Ks[k][kg * 4 + c * 32];
            fma2(o[c].u[0], p2, v.u[0]);
            fma2(o[c].u[1], p2, v.u[1]);
        }
    }
#pragma unroll
    for (int c = 0; c < 2; c++) {
        float4 r4;
        r4.x = o[c].f.x * invl; r4.y = o[c].f.y * invl;
        r4.z = o[c].f.z * invl; r4.w = o[c].f.w * invl;
        *(float4*)&g_attn[base + qi][hc + kg * 4 + c * 32] = r4;
    }
}

// =============== refine head, stage A ===============
__global__ void __launch_bounds__(256) refineA_kernel(
    const float* __restrict__ Wemb, const float* __restrict__ bemb,
    const float* __restrict__ Wr1, const float* __restrict__ br1,
    int step, int first) {
    int b = blockIdx.x >> 4, part = blockIdx.x & 15;
    __shared__ float comb[1024];
    __shared__ float cur[32];
    int tid = threadIdx.x;
    int ptr = TH + step;
    if (tid < 32) cur[tid] = first ? g_buf[b][ptr - 1][tid] : g_cur[b][tid];
    __syncthreads();
    for (int d = tid; d < 512; d += 256) {
        const float* w = &Wemb[d * 32];
        float s = 0.0f;
#pragma unroll
        for (int i = 0; i < 32; i += 4) {
            float4 wv = ldg4(&w[i]);
            s += wv.x * cur[i] + wv.y * cur[i + 1] + wv.z * cur[i + 2] + wv.w * cur[i + 3];
        }
        comb[d] = (s + __ldg(&bemb[d])) * EMB_SCALE;
    }
    for (int d = tid; d < 512; d += 256) comb[512 + d] = g_h[b * T + ptr - 1][d];
    __syncthreads();

    int r = part * 128 + (tid >> 1);
    int half = tid & 1;
    const float* w = &Wr1[r * 1024 + half * 512];
    const float* cb = &comb[half * 512];
    u64 a0 = pack2(0.f, 0.f), a1 = pack2(0.f, 0.f);
    for (int i = 0; i < 512; i += 4) {
        F4U wv; wv.f = ldg4(&w[i]);
        F4U cv; cv.f = *(const float4*)&cb[i];
        fma2(a0, wv.u[0], cv.u[0]);
        fma2(a1, wv.u[1], cv.u[1]);
    }
    float2 x0 = unpack2(a0), x1 = unpack2(a1);
    float s = x0.x + x0.y + x1.x + x1.y;
    s += __shfl_xor_sync(~0u, s, 1);
    if (half == 0) g_ffr[b][r] = gelu_fast(s + __ldg(&br1[r]));
}

// =============== refine head, stage B ===============
__global__ void __launch_bounds__(256) refineB_kernel(
    const float* __restrict__ Wr2, const float* __restrict__ br2,
    float* __restrict__ out, int step, int first, int last) {
    int b = blockIdx.x;
    int tid = threadIdx.x;
    __shared__ float ff[2048];
    for (int i = tid; i < 2048; i += 256) ff[i] = g_ffr[b][i];
    __syncthreads();
    int i = tid >> 3, part = tid & 7;
    const float* w = &Wr2[i * 2048 + part * 256];
    const float* f = &ff[part * 256];
    u64 a0 = pack2(0.f, 0.f), a1 = pack2(0.f, 0.f);
    for (int j = 0; j < 256; j += 4) {
        F4U wv; wv.f = ldg4(&w[j]);
        F4U fv; fv.f = *(const float4*)&f[j];
        fma2(a0, wv.u[0], fv.u[0]);
        fma2(a1, wv.u[1], fv.u[1]);
    }
    float2 x0 = unpack2(a0), x1 = unpack2(a1);
    float s = x0.x + x0.y + x1.x + x1.y;
    s += __shfl_xor_sync(~0u, s, 1);
    s += __shfl_xor_sync(~0u, s, 2);
    s += __shfl_xor_sync(~0u, s, 4);
    if (part == 0) {
        int ptr = TH + step;
        float basev = first ? g_buf[b][ptr - 1][i] : g_cur[b][i];
        float nv = basev + s + __ldg(&br2[i]);
        g_cur[b][i] = nv;
        if (last) {
            g_buf[b][ptr][i] = nv;
            out[(b * STEPS + step) * D_IN + i] = nv;
        }
    }
}

// =============== host orchestration ===============
extern "C" void kernel_launch(void* const* d_in, const int* in_sizes, int n_in,
                              void* d_out, int out_size) {
    int o = (n_in >= 20) ? 1 : 0;   // "steps" scalar occupies index 1 if present
    const float* history = (const float*)d_in[0];
    const float* Wemb = (const float*)d_in[1 + o];
    const float* bemb = (const float*)d_in[2 + o];
    const float* Wq = (const float*)d_in[3 + o];
    const float* Wk = (const float*)d_in[4 + o];
    const float* Wv = (const float*)d_in[5 + o];
    const float* Wo = (const float*)d_in[6 + o];
    const float* ln1g = (const float*)d_in[7 + o];
    const float* ln1b = (const float*)d_in[8 + o];
    const float* W1 = (const float*)d_in[9 + o];
    const float* b1 = (const float*)d_in[10 + o];
    const float* W2 = (const float*)d_in[11 + o];
    const float* b2 = (const float*)d_in[12 + o];
    const float* ln2g = (const float*)d_in[13 + o];
    const float* ln2b = (const float*)d_in[14 + o];
    const float* Wr1 = (const float*)d_in[15 + o];
    const float* br1 = (const float*)d_in[16 + o];
    const float* Wr2 = (const float*)d_in[17 + o];
    const float* br2 = (const float*)d_in[18 + o];
    float* out = (float*)d_out;

    void* p;
    cudaGetSymbolAddress(&p, g_h);    float* ph = (float*)p;
    cudaGetSymbolAddress(&p, g_q);    float* pq = (float*)p;
    cudaGetSymbolAddress(&p, g_k);    float* pk = (float*)p;
    cudaGetSymbolAddress(&p, g_v);    float* pv = (float*)p;
    cudaGetSymbolAddress(&p, g_q2);   float* pq2 = (float*)p;
    cudaGetSymbolAddress(&p, g_k2);   float* pk2 = (float*)p;
    cudaGetSymbolAddress(&p, g_v2);   float* pv2 = (float*)p;
    cudaGetSymbolAddress(&p, g_attn); float* pat = (float*)p;
    cudaGetSymbolAddress(&p, g_ff);   float* pff = (float*)p;
    cudaGetSymbolAddress(&p, g_part); float* ppart = (float*)p;
    float* pp0 = ppart;
    float* pp1 = ppart + M * D_MODEL;
    float* pp2 = ppart + 2 * M * D_MODEL;
    float* pp3 = ppart + 3 * M * D_MODEL;

    cudaFuncSetAttribute(attn_kernel, cudaFuncAttributeMaxDynamicSharedMemorySize,
                         ATTN_SMEM);

    O6 oqkv = {{pq, pq2, pk, pk2, pv, pv2}};
    O6 owo = {{pp0, pp1, nullptr, nullptr, nullptr, nullptr}};
    O6 off1 = {{pff, nullptr, nullptr, nullptr, nullptr, nullptr}};
    O6 off2 = {{pp0, pp1, pp2, pp3, nullptr, nullptr}};
    P4 lp1 = {{pp0, pp1, nullptr, nullptr}};
    P4 lp2 = {{pp0, pp1, pp2, pp3}};

    init_buf_kernel<<<B, 256>>>(history);

    for (int step = 0; step < STEPS; step++) {
        embed_kernel<<<M, 128>>>(Wemb, bemb);
        for (int l = 0; l < N_LAYERS; l++) {
            const float* wq = Wq + l * D_MODEL * D_MODEL;
            const float* wk = Wk + l * D_MODEL * D_MODEL;
            const float* wv = Wv + l * D_MODEL * D_MODEL;
            const float* wo = Wo + l * D_MODEL * D_MODEL;
            const float* w1 = W1 + l * D_FF * D_MODEL;
            const float* w2 = W2 + l * D_MODEL * D_FF;

            // QKV: 3 mats x split-K2, 64x64 tiles -> 384 blocks
            gemm2_kernel<2, 0><<<dim3(8, 8, 6), 256>>>(
                ph, wq, wk, wv, oqkv, nullptr, 512, 512, 256);
            attn_kernel<<<128, 256, ATTN_SMEM>>>();
            // Wo: split-K2 -> 128 blocks; residual+partial-sum fused into ln1
            gemm2_kernel<2, 0><<<dim3(8, 8, 2), 256>>>(
                pat, wo, wo, wo, owo, nullptr, 512, 512, 256);
            ln_fuse_kernel<2, false><<<128, 128>>>(
                ph, lp1, nullptr, ln1g + l * 512, ln1b + l * 512, ph);
            // FFN1: full-K, gelu+bias epilogue -> 256 blocks
            gemm2_kernel<1, 1><<<dim3(32, 8, 1), 256>>>(
                ph, w1, w1, w1, off1, b1 + l * D_FF, 2048, 512, 512);
            // FFN2: split-K4 -> 256 blocks; bias+residual+partials fused into ln2
            gemm2_kernel<4, 0><<<dim3(8, 8, 4), 256>>>(
                pff, w2, w2, w2, off2, nullptr, 512, 2048, 512);
            ln_fuse_kernel<4, true><<<128, 128>>>(
                ph, lp2, b2 + l * 512, ln2g + l * 512, ln2b + l * 512, ph);
        }
        for (int s = 0; s < N_SUB; s++) {
            refineA_kernel<<<64, 256>>>(Wemb, bemb, Wr1, br1, step, s == 0);
            refineB_kernel<<<4, 256>>>(Wr2, br2, out, step, s == 0, s == N_SUB - 1);
        }
    }
}